// round 2
// baseline (speedup 1.0000x reference)
#include <cuda_runtime.h>

// Problem constants
#define NS 131072
#define DD 16
#define RR 32
#define OO 10
#define EPSV 1e-8f

#define TPB 128   // threads per block, 1 sample per thread -> grid 1024

// ---------------- packed f32x2 helpers (Blackwell) ----------------
__device__ __forceinline__ long long pk2(float a, float b) {
    long long r;
    asm("mov.b64 %0, {%1, %2};" : "=l"(r) : "f"(a), "f"(b));
    return r;
}
__device__ __forceinline__ void unpk2(long long v, float& a, float& b) {
    asm("mov.b64 {%0, %1}, %2;" : "=f"(a), "=f"(b) : "l"(v));
}
__device__ __forceinline__ long long f2fma(long long a, long long b, long long c) {
    long long d;
    asm("fma.rn.f32x2 %0, %1, %2, %3;" : "=l"(d) : "l"(a), "l"(b), "l"(c));
    return d;
}
__device__ __forceinline__ long long f2sub(long long a, long long b) {
    long long d;
    asm("sub.rn.f32x2 %0, %1, %2;" : "=l"(d) : "l"(a), "l"(b));
    return d;
}
__device__ __forceinline__ long long f2mul(long long a, long long b) {
    long long d;
    asm("mul.rn.f32x2 %0, %1, %2;" : "=l"(d) : "l"(a), "l"(b));
    return d;
}
__device__ __forceinline__ long long f2add(long long a, long long b) {
    long long d;
    asm("add.rn.f32x2 %0, %1, %2;" : "=l"(d) : "l"(a), "l"(b));
    return d;
}

__global__ void __launch_bounds__(TPB, 6)
anfis_kernel(const float* __restrict__ X,
             const float* __restrict__ centers,
             const float* __restrict__ sigmas,
             const float* __restrict__ coeffs,
             float* __restrict__ out) {
    // [r][0..15] = centers, [r][16..31] = -1/(2 sigma^2); contiguous scalar
    // floats so dimension-pairs read directly as long long (LDS.64/128)
    __shared__ __align__(16) float sCK[RR][32];                // 4 KB
    __shared__ __align__(16) float sW[RR * 17 * 12];           // o padded 10->12, 25.5 KB

    const int tid = threadIdx.x;

    for (int i = tid; i < RR * DD; i += TPB) {
        int r = i >> 4, d = i & 15;
        float c = centers[i];
        float s = sigmas[i];
        sCK[r][d] = c;
        sCK[r][16 + d] = -0.5f / (s * s);
    }
    for (int i = tid; i < RR * (DD + 1) * OO; i += TPB) {
        int r = i / 170;
        int rem = i - r * 170;
        int row = rem / 10;
        int o = rem - row * 10;
        sW[r * 204 + row * 12 + o] = coeffs[i];
    }
    __syncthreads();

    const int n = blockIdx.x * TPB + tid;

    // load input row (64B, float4) -> scalars + dimension-pair packs
    float x[16];
    {
        const float4* p = (const float4*)(X + (size_t)n * DD);
        float4 a = p[0], b = p[1], c = p[2], d = p[3];
        x[0] = a.x; x[1] = a.y; x[2] = a.z; x[3] = a.w;
        x[4] = b.x; x[5] = b.y; x[6] = b.z; x[7] = b.w;
        x[8] = c.x; x[9] = c.y; x[10] = c.z; x[11] = c.w;
        x[12] = d.x; x[13] = d.y; x[14] = d.z; x[15] = d.w;
    }
    long long xp[8];
    #pragma unroll
    for (int j = 0; j < 8; j++) xp[j] = pk2(x[2 * j], x[2 * j + 1]);

    long long acc[5];
    #pragma unroll
    for (int j = 0; j < 5; j++) acc[j] = 0LL;
    float ssum = 0.0f;

    #pragma unroll 1
    for (int r = 0; r < RR; r++) {
        // ---- rule strength, lanes = (even dim, odd dim) pairs ----
        const long long* cp = (const long long*)(&sCK[r][0]);   // 8 packed c-pairs
        const long long* kp = (const long long*)(&sCK[r][16]);  // 8 packed k-pairs
        long long ea = 0LL, eb = 0LL;
        #pragma unroll
        for (int j = 0; j < 8; j += 2) {
            long long dfa = f2sub(xp[j], cp[j]);
            ea = f2fma(f2mul(dfa, dfa), kp[j], ea);
            long long dfb = f2sub(xp[j + 1], cp[j + 1]);
            eb = f2fma(f2mul(dfb, dfb), kp[j + 1], eb);
        }
        float e0, e1;
        unpk2(f2add(ea, eb), e0, e1);
        float s = __expf(e0 + e1);
        ssum += s;

        // ---- consequent: t[o-pair] = b[r,o] + sum_d x_d * C[r,d,o] ----
        const float* Crow = sW + r * 204;
        long long t[5];
        {
            longlong2 bA = *(const longlong2*)(Crow + 192);  // o0..o3 (bias row)
            longlong2 bB = *(const longlong2*)(Crow + 196);  // o4..o7
            long long bC = *(const long long*)(Crow + 200);  // o8,o9
            t[0] = bA.x; t[1] = bA.y; t[2] = bB.x; t[3] = bB.y; t[4] = bC;
        }
        #pragma unroll
        for (int d = 0; d < DD; d++) {
            const float* p = Crow + d * 12;
            longlong2 cA = *(const longlong2*)p;        // (o0,o1),(o2,o3)
            longlong2 cB = *(const longlong2*)(p + 4);  // (o4,o5),(o6,o7)
            long long cC = *(const long long*)(p + 8);  // (o8,o9)
            long long xa = pk2(x[d], x[d]);
            t[0] = f2fma(xa, cA.x, t[0]);
            t[1] = f2fma(xa, cA.y, t[1]);
            t[2] = f2fma(xa, cB.x, t[2]);
            t[3] = f2fma(xa, cB.y, t[3]);
            t[4] = f2fma(xa, cC, t[4]);
        }

        // ---- acc += s_r * t (unnormalized; divide at the end) ----
        long long sp = pk2(s, s);
        #pragma unroll
        for (int j = 0; j < 5; j++) acc[j] = f2fma(sp, t[j], acc[j]);
    }

    // ---- finalize: normalize, softmax(10), store ----
    float v[10];
    #pragma unroll
    for (int j = 0; j < 5; j++) unpk2(acc[j], v[2 * j], v[2 * j + 1]);

    float inv = __fdividef(1.0f, ssum + EPSV);
    #pragma unroll
    for (int i = 0; i < 10; i++) v[i] *= inv;

    float m = v[0];
    #pragma unroll
    for (int i = 1; i < 10; i++) m = fmaxf(m, v[i]);

    float se = 0.0f;
    #pragma unroll
    for (int i = 0; i < 10; i++) { v[i] = __expf(v[i] - m); se += v[i]; }
    float is = __fdividef(1.0f, se);

    float2* o2 = (float2*)(out + (size_t)n * OO);  // 40B row base -> 8B aligned
    #pragma unroll
    for (int j = 0; j < 5; j++) {
        float2 w; w.x = v[2 * j] * is; w.y = v[2 * j + 1] * is;
        o2[j] = w;
    }
}

extern "C" void kernel_launch(void* const* d_in, const int* in_sizes, int n_in,
                              void* d_out, int out_size) {
    const float* X = (const float*)d_in[0];
    const float* centers = (const float*)d_in[1];
    const float* sigmas = (const float*)d_in[2];
    const float* coeffs = (const float*)d_in[3];
    float* out = (float*)d_out;

    const int blocks = NS / TPB;  // 1024
    anfis_kernel<<<blocks, TPB>>>(X, centers, sigmas, coeffs, out);
}